// round 15
// baseline (speedup 1.0000x reference)
#include <cuda_runtime.h>
#include <cuda_fp16.h>

// Gaussian-splat render, round 11: occupancy-doubling discriminator.
//   out[n,c] = sum_m exp(-0.5 * d^T C_m^-1 d) * cols[m,c]
//
// R10 (35.6us) fits two models: (a) stall-bound at 4 warps/SMSP, or
// (b) MUFU-bound with ex2.f16x2 at rt16. This round halves the warp tile
// (32 pixels, mt=2 -> ~60 regs) and doubles warps: BLK=1024, 8 w/SMSP.
// CTA = one 64-pixel group = 16 G-slices x 2 pixel-halves.
// If (a): ~26-30us. If (b): flat -> MUFU floor confirmed.

typedef unsigned long long u64;

static constexpr int N_GAUSS  = 2048;
static constexpr int N_CHUNK  = 128;    // 16 Gaussians per chunk
static constexpr int N_GROUP  = 1024;   // 64 pixels per group
static constexpr int BLK      = 1024;   // 32 warps: 16 slices x 2 halves
static constexpr int GRID     = 148;
static constexpr int ROUNDS   = 7;      // ceil(1024/148)

// coeffs: [128 chunks][4 qc][12 u32]  (A:5, B:5, 2 pad)
static constexpr int COEF_U32  = N_CHUNK * 4 * 12;   // 6144
static constexpr int BFRAG_U32 = N_CHUNK * 32 * 2;   // 8192
static constexpr int TAB_U32   = COEF_U32 + BFRAG_U32; // 14336
static constexpr size_t SMEM_BYTES = TAB_U32 * 4 + 16 * 192 * 4; // 69632

__device__ unsigned g_tab2[TAB_U32];

__device__ __forceinline__ unsigned h2u(__half2 h) {
    return *reinterpret_cast<unsigned*>(&h);
}
__device__ __forceinline__ __half2 u2h(unsigned u) {
    return *reinterpret_cast<__half2*>(&u);
}
__device__ __forceinline__ unsigned ex2_h2(unsigned v) {
    unsigned r; asm("ex2.approx.f16x2 %0, %1;" : "=r"(r) : "r"(v)); return r;
}

// ---- Prep: Cholesky coeff pairs (vector layout) + mma B-fragment colors ----
__global__ void prep_kernel(const float* __restrict__ mus,
                            const float* __restrict__ covs,
                            const float* __restrict__ cols)
{
    int idx = blockIdx.x * blockDim.x + threadIdx.x;

    // B-fragments: one thread per (chunk, lane)
    if (idx < N_CHUNK * 32) {
        int chunk = idx >> 5, t = idx & 31;
        int c  = t >> 2;              // mma column = color index (0..7)
        int p0 = t & 3, p1 = (t & 3) + 4;
        int gA0 = chunk * 16 + 2 * p0, gA1 = gA0 + 1;
        int gB0 = chunk * 16 + 2 * p1, gB1 = gB0 + 1;
        float b00 = (c < 3) ? cols[gA0 * 3 + c] : 0.f;
        float b01 = (c < 3) ? cols[gA1 * 3 + c] : 0.f;
        float b10 = (c < 3) ? cols[gB0 * 3 + c] : 0.f;
        float b11 = (c < 3) ? cols[gB1 * 3 + c] : 0.f;
        g_tab2[COEF_U32 + chunk * 64 + t * 2 + 0] = h2u(__floats2half2_rn(b00, b01));
        g_tab2[COEF_U32 + chunk * 64 + t * 2 + 1] = h2u(__floats2half2_rn(b10, b11));
    }

    // coefficient pairs: one thread per G-pair (1024)
    if (idx < N_GAUSS / 2) {
        int chunk = idx >> 3, p = idx & 7;
        int g = p & 3;
        bool isB = (p >= 4);
        float v[2][5];
        #pragma unroll
        for (int h = 0; h < 2; ++h) {
            int m = chunk * 16 + 2 * p + h;
            const float k = 0.72134752044448170368f;   // 0.5 * log2(e)
            float2 mu = ((const float2*)mus)[m];
            float4 cv = ((const float4*)covs)[m];      // [a, b, b, c]
            float a = cv.x, b = cv.y, c = cv.w;
            float inv_det = 1.0f / (a * c - b * b);
            float p00 =  c * inv_det * k;
            float p01 = -b * inv_det * k;
            float p11 =  a * inv_det * k;
            float r11 = sqrtf(p00);
            float r12 = p01 / r11;
            float r22 = sqrtf(fmaxf(p11 - r12 * r12, 0.f));
            v[h][0] = r11;
            v[h][1] = r12;
            v[h][2] = r22;
            v[h][3] = -(r11 * mu.x + r12 * mu.y);
            v[h][4] = -(r22 * mu.y);
        }
        unsigned* base = g_tab2 + chunk * 48 + g * 12;
        #pragma unroll
        for (int c = 0; c < 5; ++c) {
            unsigned val = h2u(__floats2half2_rn(v[0][c], v[1][c]));
            base[(isB ? 5 : 0) + c] = val;
        }
    }
}

// quadratic eval -> fp16x2 weight exp2(-(e1^2+e2^2)) for (one pixel, two G)
__device__ __forceinline__ unsigned evalw(__half2 X, __half2 Y,
                                          __half2 r11, __half2 r12, __half2 r22,
                                          __half2 m1, __half2 m2)
{
    __half2 e1 = __hfma2(r11, X, __hfma2(r12, Y, m1));
    __half2 e2 = __hfma2(r22, Y, m2);
    __half2 tp = __hfma2(__hneg2(e2), e2, __hmul2(__hneg2(e1), e1));
    return ex2_h2(h2u(tp));
}

__device__ __forceinline__ void mma16816(float& d0, float& d1, float& d2, float& d3,
                                         unsigned a0, unsigned a1, unsigned a2, unsigned a3,
                                         unsigned b0, unsigned b1)
{
    asm("mma.sync.aligned.m16n8k16.row.col.f32.f16.f16.f32 "
        "{%0,%1,%2,%3}, {%4,%5,%6,%7}, {%8,%9}, {%0,%1,%2,%3};"
        : "+f"(d0), "+f"(d1), "+f"(d2), "+f"(d3)
        : "r"(a0), "r"(a1), "r"(a2), "r"(a3), "r"(b0), "r"(b1));
}

// ---- Main render ----
__global__ __launch_bounds__(BLK, 1)
void render_kernel(const float* __restrict__ x, float* __restrict__ out)
{
    extern __shared__ unsigned sh[];
    const int tid = threadIdx.x;
    const int wid = tid >> 5;
    const int slice = wid & 15;            // Gaussian slice (0..15)
    const int phalf = wid >> 4;            // pixel half (0..1): m-tiles 2p, 2p+1
    const int lane = tid & 31;
    const int qr = lane >> 2;              // fragment row base (0..7)
    const int qc = lane & 3;               // fragment col-pair group (0..3)

    // bulk copy tables into shared
    {
        const uint4* src = (const uint4*)g_tab2;
        uint4* dst = (uint4*)sh;
        for (int i = tid; i < TAB_U32 / 4; i += BLK) dst[i] = src[i];
    }
    float* red = (float*)(sh + TAB_U32);   // [16 slices][192]
    __syncthreads();

    for (int rnd = 0; rnd < ROUNDS; ++rnd) {
        const int group = blockIdx.x + GRID * rnd;
        const bool act = (group < N_GROUP);

        if (act) {
            // this warp's 32 pixels: m-tiles mt = 2*phalf + k, k=0..1
            __half2 Xh[4], Yh[4];
            #pragma unroll
            for (int k = 0; k < 2; ++k) {
                #pragma unroll
                for (int h = 0; h < 2; ++h) {
                    int pix = group * 64 + (2 * phalf + k) * 16 + qr + h * 8;
                    float2 v = ((const float2*)x)[pix];
                    Xh[k * 2 + h] = __floats2half2_rn(v.x, v.x);
                    Yh[k * 2 + h] = __floats2half2_rn(v.y, v.y);
                }
            }

            float d[2][4];
            d[0][0] = d[0][1] = d[0][2] = d[0][3] = 0.f;
            d[1][0] = d[1][1] = d[1][2] = d[1][3] = 0.f;

            for (int j = 0; j < 8; ++j) {
                const int chunk = slice * 8 + j;
                const unsigned* cp = sh + chunk * 48 + qc * 12;
                uint4 w0 = *(const uint4*)(cp);        // A r11 r12 r22 m1
                uint4 w1 = *(const uint4*)(cp + 4);    // A m2 | B r11 r12 r22
                u64  w2 = *(const u64*)(cp + 8);       // B m1 m2
                __half2 Ar11 = u2h(w0.x), Ar12 = u2h(w0.y), Ar22 = u2h(w0.z);
                __half2 Am1  = u2h(w0.w), Am2  = u2h(w1.x);
                __half2 Br11 = u2h(w1.y), Br12 = u2h(w1.z), Br22 = u2h(w1.w);
                __half2 Bm1  = u2h((unsigned)w2), Bm2 = u2h((unsigned)(w2 >> 32));

                u64 bb = *(const u64*)(sh + COEF_U32 + chunk * 64 + lane * 2);
                unsigned b0 = (unsigned)bb, b1 = (unsigned)(bb >> 32);

                #pragma unroll
                for (int k = 0; k < 2; ++k) {
                    unsigned a0 = evalw(Xh[2*k],   Yh[2*k],   Ar11, Ar12, Ar22, Am1, Am2);
                    unsigned a1 = evalw(Xh[2*k+1], Yh[2*k+1], Ar11, Ar12, Ar22, Am1, Am2);
                    unsigned a2 = evalw(Xh[2*k],   Yh[2*k],   Br11, Br12, Br22, Bm1, Bm2);
                    unsigned a3 = evalw(Xh[2*k+1], Yh[2*k+1], Br11, Br12, Br22, Bm1, Bm2);
                    mma16816(d[k][0], d[k][1], d[k][2], d[k][3],
                             a0, a1, a2, a3, b0, b1);
                }
            }

            // write this slice's partial rgb: red[slice][pix_in_grp*3 + c]
            float* rp = red + slice * 192;
            if (qc == 0) {          // cols 0,1 = R,G
                #pragma unroll
                for (int k = 0; k < 2; ++k) {
                    int mt = 2 * phalf + k;
                    int p0 = mt * 16 + qr, p1 = p0 + 8;
                    rp[p0 * 3 + 0] = d[k][0];
                    rp[p0 * 3 + 1] = d[k][1];
                    rp[p1 * 3 + 0] = d[k][2];
                    rp[p1 * 3 + 1] = d[k][3];
                }
            } else if (qc == 1) {   // col 2 = B
                #pragma unroll
                for (int k = 0; k < 2; ++k) {
                    int mt = 2 * phalf + k;
                    int p0 = mt * 16 + qr, p1 = p0 + 8;
                    rp[p0 * 3 + 2] = d[k][0];
                    rp[p1 * 3 + 2] = d[k][2];
                }
            }
        }
        __syncthreads();

        if (act && tid < 192) {
            float s = 0.f;
            #pragma unroll
            for (int w = 0; w < 16; ++w) s += red[w * 192 + tid];
            out[group * 192 + tid] = s;
        }
        __syncthreads();
    }
}

extern "C" void kernel_launch(void* const* d_in, const int* in_sizes, int n_in,
                              void* d_out, int out_size)
{
    const float* x    = (const float*)d_in[0];
    const float* mus  = (const float*)d_in[1];
    const float* covs = (const float*)d_in[2];
    const float* cols = (const float*)d_in[3];
    float* out = (float*)d_out;

    prep_kernel<<<(N_CHUNK * 32 + 255) / 256, 256>>>(mus, covs, cols);

    cudaFuncSetAttribute(render_kernel,
                         cudaFuncAttributeMaxDynamicSharedMemorySize,
                         (int)SMEM_BYTES);
    render_kernel<<<GRID, BLK, SMEM_BYTES>>>(x, out);
}